// round 16
// baseline (speedup 1.0000x reference)
#include <cuda_runtime.h>
#include <cuda_bf16.h>

// Seq2SeqLoss: label-smoothed weighted cross-entropy, mean over masked rows.
// Harness canonical dtypes:
//   [0] outputs  f32 [B*S*C] = 131072000
//   [1] gold     i32 [B*S]   = 4096
//   [2] mask     i32 [B*S]   = 4096
//   [3] weight   f32 [C]     = 32000
// output: f32 scalar
//
// Sum factorization: with lse_r = log(sum_c exp(x_rc)), dd_r = sum_c w_c x_rc,
//   sum_r loss_r = uniform*(sumW*Σlse − Σdd) + (conf−uniform)*Σ w_g (lse − x_g)
//
// Schedule (R16): warp-autonomous chunks. Evidence so far: 256-thr/8-per-SM
// CTA shape streams at ~86% in-wave (best); __syncthreads between work items
// kills persistence (R13); CTA-level tail costs 13.5% (R10). So: one
// persistent wave of 1216 CTAs, each WARP independently grid-strides over
// 16-per-row 8KB chunks (65536 total, 6.74/warp -> 96% fill), shfl-only
// reduction, per-row combine via RED slots + acq_rel counter (16th arriver
// owns the row). No __syncthreads in the hot path, no fences anywhere.

#define SMOOTHING 0.1f
#define EPSILON   1e-8f
#define SUMW_CTAS 8
#define GRID_CTAS 1216        // 152 SMs x 8 CTAs @ 32 regs = one wave
#define CHUNK_SHIFT 4         // 16 chunks per row
#define CHUNKS_PER_ROW (1 << CHUNK_SHIFT)
#define MAX_ROWS  8192

__device__ float        g_row_s[MAX_ROWS];
__device__ float        g_row_d[MAX_ROWS];
__device__ unsigned int g_row_cnt[MAX_ROWS];
__device__ float        g_sumw;
__device__ float        g_lse_acc;
__device__ float        g_dot_acc;
__device__ float        g_gold_acc;
__device__ float        g_mask_acc;
__device__ unsigned int g_done;

// All-FMA exp (no MUFU): exp(x) = 2^(x*log2e), magic-number round,
// degree-5 poly for 2^f on [-0.5,0.5] (rel err ~2.4e-6), exponent splice.
// PROVEN BODY — do not modify.
__device__ __forceinline__ float fexp(float x) {
    float t = x * 1.4426950408889634f;
    t = fminf(fmaxf(t, -126.0f), 126.0f);
    float r = t + 12582912.0f;
    int   eb = __float_as_int(r) << 23;
    float nf = r - 12582912.0f;
    float f  = t - nf;
    float p  = 1.3333558146428443e-3f;
    p = fmaf(p, f, 9.6181291076284772e-3f);
    p = fmaf(p, f, 5.5504108664821580e-2f);
    p = fmaf(p, f, 2.4022650695910072e-1f);
    p = fmaf(p, f, 6.9314718055994531e-1f);
    p = fmaf(p, f, 1.0f);
    return __int_as_float(__float_as_int(p) + eb);
}

__device__ __forceinline__ float warp_sum(float v) {
    #pragma unroll
    for (int o = 16; o > 0; o >>= 1) v += __shfl_xor_sync(0xffffffffu, v, o);
    return v;
}

// acq_rel counter bump: release publishes this thread's prior REDs; acquire
// on the winning bump makes peers' REDs visible. No CCTL.IVALL L1 flush.
__device__ __forceinline__ unsigned int atom_inc_acqrel(unsigned int* p) {
    unsigned int old;
    asm volatile("atom.acq_rel.gpu.global.add.u32 %0, [%1], 1;"
                 : "=r"(old) : "l"(p) : "memory");
    return old;
}

__device__ __forceinline__ void arrive_and_maybe_finalize(
    float* __restrict__ out, int C, unsigned int total_arrivals)
{
    unsigned int prev = atom_inc_acqrel(&g_done);
    if (prev == total_arrivals - 1u) {
        float sumw = __ldcg(&g_sumw);
        float lse  = __ldcg(&g_lse_acc);
        float dot  = __ldcg(&g_dot_acc);
        float gld  = __ldcg(&g_gold_acc);
        float msk  = __ldcg(&g_mask_acc);

        const float uniform = SMOOTHING / (float)(C - 1);
        const float conf    = 1.0f - SMOOTHING;
        const float cmu     = conf - uniform;
        float loss_sum = uniform * fmaf(sumw, lse, -dot) + cmu * gld;
        out[0] = loss_sum / (msk + EPSILON);

        // reset for next graph replay (deterministic)
        __stcg(&g_sumw, 0.0f);
        __stcg(&g_lse_acc, 0.0f);
        __stcg(&g_dot_acc, 0.0f);
        __stcg(&g_gold_acc, 0.0f);
        __stcg(&g_mask_acc, 0.0f);
        unsigned int z = 0u;
        asm volatile("st.global.cg.u32 [%0], %1;" :: "l"(&g_done), "r"(z) : "memory");
    }
}

// Persistent single-wave grid; warps stream chunks independently.
__global__ __launch_bounds__(256, 8) void row_loss_kernel(
    const float* __restrict__ logits,
    const int*   __restrict__ gold,
    const int*   __restrict__ mask,
    const float* __restrict__ weight,
    float* __restrict__ out,
    int C4, int C, int N)
{
    const int tid   = threadIdx.x;
    const int lane  = tid & 31;
    const int gwarp = blockIdx.x * 8 + (tid >> 5);
    const int nwarps = GRID_CTAS * 8;
    const float4* wp = reinterpret_cast<const float4*>(weight);
    const int CHUNK_F4 = C4 >> CHUNK_SHIFT;          // float4s per chunk

    // ---- sumW: first 8 warps each sum a weight slice (lane-strided) ----
    if (gwarp < SUMW_CTAS) {
        const int per = (C4 + SUMW_CTAS - 1) / SUMW_CTAS;
        const int lo  = gwarp * per;
        const int hi  = min(lo + per, C4);
        float w = 0.0f;
        for (int i = lo + lane; i < hi; i += 32) {
            float4 v = __ldg(wp + i);
            w += v.x + v.y + v.z + v.w;
        }
        w = warp_sum(w);
        if (lane == 0) atomicAdd(&g_sumw, w);
    }

    // ---- warp-autonomous chunk loop (no __syncthreads, no fences) ----
    const int total_chunks = N << CHUNK_SHIFT;
    for (int c = gwarp; c < total_chunks; c += nwarps) {
        const int row  = c >> CHUNK_SHIFT;
        const int part = c & (CHUNKS_PER_ROW - 1);
        const float4* lp = reinterpret_cast<const float4*>(logits)
                         + (size_t)row * C4 + part * CHUNK_F4;
        const float4* wh = wp + part * CHUNK_F4;

        // proven streaming loop body (warp-strided)
        float s = 0.0f, d = 0.0f;
        #pragma unroll 4
        for (int i = lane; i < CHUNK_F4; i += 32) {
            float4 x = __ldcs(lp + i);
            float4 w = __ldg(wh + i);
            d = fmaf(x.x, w.x, d);
            d = fmaf(x.y, w.y, d);
            d = fmaf(x.z, w.z, d);
            d = fmaf(x.w, w.w, d);
            s += fexp(x.x);
            s += fexp(x.y);
            s += fexp(x.z);
            s += fexp(x.w);
        }

        s = warp_sum(s);
        d = warp_sum(d);
        if (lane == 0) {
            atomicAdd(&g_row_s[row], s);
            atomicAdd(&g_row_d[row], d);
            unsigned int prev = atom_inc_acqrel(&g_row_cnt[row]);
            if (prev == CHUNKS_PER_ROW - 1u) {   // last arriver owns the row
                float stot = __ldcg(&g_row_s[row]);
                float dtot = __ldcg(&g_row_d[row]);
                __stcg(&g_row_s[row], 0.0f);     // reset for next replay
                __stcg(&g_row_d[row], 0.0f);
                unsigned int z = 0u;
                asm volatile("st.global.cg.u32 [%0], %1;"
                             :: "l"(&g_row_cnt[row]), "r"(z) : "memory");
                if (mask[row] != 0) {
                    int   g   = gold[row];
                    float xg  = __ldg(logits + (size_t)row * C + (size_t)g);
                    float wg  = __ldg(weight + g);
                    float lse = logf(stot);
                    atomicAdd(&g_lse_acc,  lse);
                    atomicAdd(&g_dot_acc,  dtot);
                    atomicAdd(&g_gold_acc, wg * (lse - xg));
                    atomicAdd(&g_mask_acc, 1.0f);
                }
            }
        }
    }

    // end-of-kernel only: CTA-granular arrival (keeps counter traffic low)
    __syncthreads();
    if (tid == 0) arrive_and_maybe_finalize(out, C, (unsigned int)GRID_CTAS);
}

extern "C" void kernel_launch(void* const* d_in, const int* in_sizes, int n_in,
                              void* d_out, int out_size)
{
    const float* logits = (const float*)d_in[0];
    const int*   gold   = (const int*)d_in[1];
    const int*   mask   = (const int*)d_in[2];
    const float* weight = (const float*)d_in[3];
    float*       out    = (float*)d_out;

    const int N = in_sizes[1];     // B*S rows
    const int C = in_sizes[3];     // classes
    const int C4 = C / 4;

    row_loss_kernel<<<GRID_CTAS, 256>>>(logits, gold, mask, weight, out, C4, C, N);
}

// round 17
// speedup vs baseline: 1.2311x; 1.2311x over previous
#include <cuda_runtime.h>
#include <cuda_bf16.h>

// Seq2SeqLoss: label-smoothed weighted cross-entropy, mean over masked rows.
// Harness canonical dtypes:
//   [0] outputs  f32 [B*S*C] = 131072000
//   [1] gold     i32 [B*S]   = 4096
//   [2] mask     i32 [B*S]   = 4096
//   [3] weight   f32 [C]     = 32000
// output: f32 scalar
//
// Sum factorization: with lse_r = log(sum_c exp(x_rc)), dd_r = sum_c w_c x_rc,
//   sum_r loss_r = uniform*(sumW*Σlse − Σdd) + (conf−uniform)*Σ w_g (lse − x_g)
//
// Schedule (R17): 4 contiguous rows fused per CTA, interleaved in ONE inner
// loop (no sequential row loop, no mid-kernel barriers — the R12/R13 failure
// mode). Grid 1024+8 with __launch_bounds__(256,7) (<=36 regs) -> 7 CTAs/SM
// -> the ENTIRE grid is resident in a single wave: zero wave quantization
// (R10's only loss). Long 31-iteration streams preserve steady-state MLP
// (the R11/R14/R16 failure mode), and 4 independent streams/thread raise MLP.

#define SMOOTHING 0.1f
#define EPSILON   1e-8f
#define SUMW_CTAS 8
#define ROWS_PER_CTA 4

__device__ float        g_sumw;
__device__ float        g_lse_acc;
__device__ float        g_dot_acc;
__device__ float        g_gold_acc;
__device__ float        g_mask_acc;
__device__ unsigned int g_done;

// All-FMA exp (no MUFU): exp(x) = 2^(x*log2e), magic-number round,
// degree-5 poly for 2^f on [-0.5,0.5] (rel err ~2.4e-6), exponent splice.
// PROVEN BODY — do not modify.
__device__ __forceinline__ float fexp(float x) {
    float t = x * 1.4426950408889634f;
    t = fminf(fmaxf(t, -126.0f), 126.0f);
    float r = t + 12582912.0f;
    int   eb = __float_as_int(r) << 23;
    float nf = r - 12582912.0f;
    float f  = t - nf;
    float p  = 1.3333558146428443e-3f;
    p = fmaf(p, f, 9.6181291076284772e-3f);
    p = fmaf(p, f, 5.5504108664821580e-2f);
    p = fmaf(p, f, 2.4022650695910072e-1f);
    p = fmaf(p, f, 6.9314718055994531e-1f);
    p = fmaf(p, f, 1.0f);
    return __int_as_float(__float_as_int(p) + eb);
}

__device__ __forceinline__ float warp_sum(float v) {
    #pragma unroll
    for (int o = 16; o > 0; o >>= 1) v += __shfl_xor_sync(0xffffffffu, v, o);
    return v;
}

// acq_rel counter bump: release publishes this CTA's prior REDs; acquire on
// the final bump makes all CTAs' REDs visible. No fences -> no CCTL.IVALL.
__device__ __forceinline__ unsigned int atom_inc_acqrel(unsigned int* p) {
    unsigned int old;
    asm volatile("atom.acq_rel.gpu.global.add.u32 %0, [%1], 1;"
                 : "=r"(old) : "l"(p) : "memory");
    return old;
}

__device__ __forceinline__ void arrive_and_maybe_finalize(
    float* __restrict__ out, int C, unsigned int total_ctas)
{
    unsigned int prev = atom_inc_acqrel(&g_done);
    if (prev == total_ctas - 1u) {
        float sumw = __ldcg(&g_sumw);
        float lse  = __ldcg(&g_lse_acc);
        float dot  = __ldcg(&g_dot_acc);
        float gld  = __ldcg(&g_gold_acc);
        float msk  = __ldcg(&g_mask_acc);

        const float uniform = SMOOTHING / (float)(C - 1);
        const float conf    = 1.0f - SMOOTHING;
        const float cmu     = conf - uniform;
        float loss_sum = uniform * fmaf(sumw, lse, -dot) + cmu * gld;
        out[0] = loss_sum / (msk + EPSILON);

        // reset for next graph replay (deterministic)
        __stcg(&g_sumw, 0.0f);
        __stcg(&g_lse_acc, 0.0f);
        __stcg(&g_dot_acc, 0.0f);
        __stcg(&g_gold_acc, 0.0f);
        __stcg(&g_mask_acc, 0.0f);
        unsigned int z = 0u;
        asm volatile("st.global.cg.u32 [%0], %1;" :: "l"(&g_done), "r"(z) : "memory");
    }
}

// Grid = ceil(N/4) + SUMW_CTAS; min-blocks 7 pins regs <= 36 so the whole
// grid is co-resident (148 SM x 7 = 1036 slots >= 1032 CTAs).
__global__ __launch_bounds__(256, 7) void row_loss_kernel(
    const float* __restrict__ logits,
    const int*   __restrict__ gold,
    const int*   __restrict__ mask,
    const float* __restrict__ weight,
    float* __restrict__ out,
    int C4, int C, int N, int ROWQ)
{
    const int bid = blockIdx.x;
    const int tid = threadIdx.x;
    const float4* wp = reinterpret_cast<const float4*>(weight);
    const unsigned int total_ctas = (unsigned int)(ROWQ + SUMW_CTAS);

    __shared__ float sh_s[ROWS_PER_CTA][8], sh_d[ROWS_PER_CTA][8];
    const int wid = tid >> 5;
    const int lid = tid & 31;

    if (bid >= ROWQ) {
        // ---- sumW slice CTA ----
        const int slice = bid - ROWQ;
        const int per   = (C4 + SUMW_CTAS - 1) / SUMW_CTAS;
        const int lo    = slice * per;
        const int hi    = min(lo + per, C4);
        float w = 0.0f;
        for (int i = lo + tid; i < hi; i += 256) {
            float4 v = __ldg(wp + i);
            w += v.x + v.y + v.z + v.w;
        }
        w = warp_sum(w);
        if (lid == 0) sh_s[0][wid] = w;
        __syncthreads();
        if (tid == 0) {
            float ww = 0.0f;
            #pragma unroll
            for (int k = 0; k < 8; k++) ww += sh_s[0][k];
            atomicAdd(&g_sumw, ww);
            arrive_and_maybe_finalize(out, C, total_ctas);
        }
        return;
    }

    // ---- 4-row fused streaming CTA ----
    const int row0 = bid * ROWS_PER_CTA;     // rows row0 .. row0+3 (contiguous)
    const float4* l0 = reinterpret_cast<const float4*>(logits) + (size_t)row0 * C4;
    const size_t  R  = (size_t)C4;           // row stride in float4s

    float s0 = 0.0f, s1 = 0.0f, s2 = 0.0f, s3 = 0.0f;
    float d0 = 0.0f, d1 = 0.0f, d2 = 0.0f, d3 = 0.0f;

    #pragma unroll 1
    for (int i = tid; i < C4; i += 256) {
        float4 w  = __ldg(wp + i);
        float4 x0 = __ldcs(l0 + i);
        float4 x1 = __ldcs(l0 + R + i);
        float4 x2 = __ldcs(l0 + 2 * R + i);
        float4 x3 = __ldcs(l0 + 3 * R + i);

        d0 = fmaf(x0.x, w.x, d0); d0 = fmaf(x0.y, w.y, d0);
        d0 = fmaf(x0.z, w.z, d0); d0 = fmaf(x0.w, w.w, d0);
        d1 = fmaf(x1.x, w.x, d1); d1 = fmaf(x1.y, w.y, d1);
        d1 = fmaf(x1.z, w.z, d1); d1 = fmaf(x1.w, w.w, d1);
        d2 = fmaf(x2.x, w.x, d2); d2 = fmaf(x2.y, w.y, d2);
        d2 = fmaf(x2.z, w.z, d2); d2 = fmaf(x2.w, w.w, d2);
        d3 = fmaf(x3.x, w.x, d3); d3 = fmaf(x3.y, w.y, d3);
        d3 = fmaf(x3.z, w.z, d3); d3 = fmaf(x3.w, w.w, d3);

        s0 += fexp(x0.x); s0 += fexp(x0.y); s0 += fexp(x0.z); s0 += fexp(x0.w);
        s1 += fexp(x1.x); s1 += fexp(x1.y); s1 += fexp(x1.z); s1 += fexp(x1.w);
        s2 += fexp(x2.x); s2 += fexp(x2.y); s2 += fexp(x2.z); s2 += fexp(x2.w);
        s3 += fexp(x3.x); s3 += fexp(x3.y); s3 += fexp(x3.z); s3 += fexp(x3.w);
    }

    s0 = warp_sum(s0); d0 = warp_sum(d0);
    s1 = warp_sum(s1); d1 = warp_sum(d1);
    s2 = warp_sum(s2); d2 = warp_sum(d2);
    s3 = warp_sum(s3); d3 = warp_sum(d3);
    if (lid == 0) {
        sh_s[0][wid] = s0; sh_d[0][wid] = d0;
        sh_s[1][wid] = s1; sh_d[1][wid] = d1;
        sh_s[2][wid] = s2; sh_d[2][wid] = d2;
        sh_s[3][wid] = s3; sh_d[3][wid] = d3;
    }
    __syncthreads();

    if (tid == 0) {
        #pragma unroll
        for (int r = 0; r < ROWS_PER_CTA; r++) {
            int row = row0 + r;
            if (row < N && mask[row] != 0) {
                float ss = 0.0f, dd = 0.0f;
                #pragma unroll
                for (int k = 0; k < 8; k++) { ss += sh_s[r][k]; dd += sh_d[r][k]; }

                int   g   = gold[row];
                float xg  = __ldg(logits + (size_t)row * C + (size_t)g);
                float wg  = __ldg(weight + g);
                float lse = logf(ss);

                atomicAdd(&g_lse_acc,  lse);
                atomicAdd(&g_dot_acc,  dd);
                atomicAdd(&g_gold_acc, wg * (lse - xg));
                atomicAdd(&g_mask_acc, 1.0f);
            }
        }
        arrive_and_maybe_finalize(out, C, total_ctas);
    }
}

extern "C" void kernel_launch(void* const* d_in, const int* in_sizes, int n_in,
                              void* d_out, int out_size)
{
    const float* logits = (const float*)d_in[0];
    const int*   gold   = (const int*)d_in[1];
    const int*   mask   = (const int*)d_in[2];
    const float* weight = (const float*)d_in[3];
    float*       out    = (float*)d_out;

    const int N = in_sizes[1];     // B*S rows
    const int C = in_sizes[3];     // classes
    const int C4 = C / 4;
    const int ROWQ = (N + ROWS_PER_CTA - 1) / ROWS_PER_CTA;

    row_loss_kernel<<<ROWQ + SUMW_CTAS, 256>>>(logits, gold, mask, weight, out, C4, C, N, ROWQ);
}